// round 9
// baseline (speedup 1.0000x reference)
#include <cuda_runtime.h>
#include <cuda_bf16.h>
#include <math_constants.h>

#define H_OUT  135
#define W_OUT  240
#define NPIX   (H_OUT * W_OUT)   // 32400
#define EPS_A  1e-8f
#define Z_CLIP 0.01f

#define MAXF   2048
#define NW     16                // warps per block == face splits
#define BLOCKT 512
#define NBLK   128               // 120 A-tiles (32r x 8c) + 8 B-tiles (7r x 30c)

// shared memory layout (dynamic):
//  sc   : float4[MAXF*3]  coeffs          = 98304 B
//  sbb  : float4[MAXF]    bboxes          = 32768 B   (reused as zf after cull)
//  zf   : float2[8][NW][32] candidates    = 32768 B   (overlays sbb)
//  sl   : int[NW][128]    cull lists      =  8192 B
#define SC_OFF   0
#define SC_BYTES (MAXF * 3 * 16)
#define BB_OFF   SC_BYTES
#define BB_BYTES (MAXF * 16)
#define SL_OFF   (BB_OFF + BB_BYTES)
#define SL_BYTES (NW * 128 * 4)
#define SMEM_TOTAL (SL_OFF + SL_BYTES)   // 139264

__device__ __forceinline__ void project_v(float vx, float vy, float vz,
                                          float& xn, float& yn) {
    float xs = 1000.0f * (-vx) / vz + 960.0f;
    float ys = 1000.0f * vy    / vz + 540.0f;
    xn = -(2.0f * xs - 1920.0f) / 1080.0f;
    yn = -(2.0f * ys - 1080.0f) / 1080.0f;
}

__device__ __forceinline__ float pix_x(int c) {
    return -(2.0f * (float)c + 1.0f - (float)W_OUT) / 135.0f;
}
__device__ __forceinline__ float pix_y(int r_out) {
    int h = H_OUT - 1 - r_out;   // undo the [::-1] row flip
    return -(2.0f * (float)h + 1.0f - (float)H_OUT) / 135.0f;
}

// a*b - c*d with two-prod compensation (~0.5 ulp)
__device__ __forceinline__ float cross_acc(float a, float b, float c, float d) {
    float p1 = a * b;
    float e1 = fmaf(a, b, -p1);
    float p2 = c * d;
    float e2 = fmaf(c, d, -p2);
    return (p1 - p2) + (e1 - e2);
}

// a0*b0 + a1*b1 + a2*b2 with two-prod + two-sum compensation
__device__ __forceinline__ float dot3_acc(float a0, float b0,
                                          float a1, float b1,
                                          float a2, float b2) {
    float p0 = a0 * b0, e0 = fmaf(a0, b0, -p0);
    float p1 = a1 * b1, e1 = fmaf(a1, b1, -p1);
    float p2 = a2 * b2, e2 = fmaf(a2, b2, -p2);
    float s1 = p0 + p1;
    float v1 = s1 - p0;
    float t1 = (p0 - (s1 - v1)) + (p1 - v1);
    float s2 = s1 + p2;
    float v2 = s2 - s1;
    float t2 = (s1 - (s2 - v2)) + (p2 - v2);
    return s2 + (t1 + t2 + e0 + e1 + e2);
}

__global__ __launch_bounds__(BLOCKT)
void raster_one_kernel(const float* __restrict__ verts,
                       const int*   __restrict__ faces,
                       float* __restrict__ out,
                       int F, int flen) {
    extern __shared__ char smem[];
    float4* sc  = (float4*)(smem + SC_OFF);
    float4* sbb = (float4*)(smem + BB_OFF);
    float2* zf  = (float2*)(smem + BB_OFF);   // overlays sbb after cull
    int*    sl  = (int*)   (smem + SL_OFF);

    // ---- phase 1: fold ALL faces into shared (every block, redundant) ----
    for (int f = threadIdx.x; f < F; f += BLOCKT) {
        int i0 = faces[3 * f + 0];
        int i1 = faces[3 * f + 1];
        int i2 = faces[3 * f + 2];

        float v0z = verts[3 * i0 + 2];
        float v1z = verts[3 * i1 + 2];
        float v2z = verts[3 * i2 + 2];

        float x0, y0, x1, y1, x2, y2;
        project_v(verts[3 * i0], verts[3 * i0 + 1], v0z, x0, y0);
        project_v(verts[3 * i1], verts[3 * i1 + 1], v1z, x1, y1);
        project_v(verts[3 * i2], verts[3 * i2 + 1], v2z, x2, y2);

        float area = (x1 - x0) * (y2 - y0) - (y1 - y0) * (x2 - x0);
        bool ok = (fabsf(area) > EPS_A) &&
                  (v0z > Z_CLIP) && (v1z > Z_CLIP) && (v2z > Z_CLIP);

        float4 C0, C1, C2, BB;
        if (ok) {
            float inv = 1.0f / area;          // fp32 reciprocal, same as reference
            float dy21 = y2 - y1, dx21 = x2 - x1;
            float dy02 = y0 - y2, dx02 = x0 - x2;
            float dy10 = y1 - y0, dx10 = x1 - x0;

            float gx0 = -dy21 * inv;
            float gy0 =  dx21 * inv;
            float k0  = cross_acc(dy21, x1, dx21, y1) * inv;
            float gx1 = -dy02 * inv;
            float gy1 =  dx02 * inv;
            float k1  = cross_acc(dy02, x2, dx02, y2) * inv;
            float gx2 = -dy10 * inv;
            float gy2 =  dx10 * inv;
            float k2  = cross_acc(dy10, x0, dx10, y0) * inv;

            float zx = dot3_acc(gx0, v0z, gx1, v1z, gx2, v2z);
            float zy = dot3_acc(gy0, v0z, gy1, v1z, gy2, v2z);
            float zk = dot3_acc(k0,  v0z, k1,  v1z, k2,  v2z);

            C0 = make_float4(gx0, gy0, k0, gx1);
            C1 = make_float4(gy1, k1, gx2, gy2);
            C2 = make_float4(k2, zx, zy, zk);
            float m = 2e-6f;
            BB = make_float4(fminf(x0, fminf(x1, x2)) - m,
                             fmaxf(x0, fmaxf(x1, x2)) + m,
                             fminf(y0, fminf(y1, y2)) - m,
                             fmaxf(y0, fmaxf(y1, y2)) + m);
        } else {
            C0 = make_float4(0.0f, 0.0f, -1.0f, 0.0f);
            C1 = make_float4(0.0f, 0.0f, 0.0f, 0.0f);
            C2 = make_float4(0.0f, 0.0f, 0.0f, 0.0f);
            BB = make_float4(CUDART_INF_F, -CUDART_INF_F,
                             CUDART_INF_F, -CUDART_INF_F);   // never passes cull
        }

        sc[f * 3 + 0] = C0;
        sc[f * 3 + 1] = C1;
        sc[f * 3 + 2] = C2;
        sbb[f] = BB;
    }
    __syncthreads();

    // ---- tile geometry for this block ----
    int w    = threadIdx.x >> 5;
    int lane = threadIdx.x & 31;
    int b    = blockIdx.x;
    bool cfgA = (b < 120);

    int r0, c0;
    float pyl, pyh, pxl, pxh;
    if (cfgA) {                      // 32 rows (lane) x 8 cols (k)
        int band = b / 30, tc = b - band * 30;
        r0 = band * 32;  c0 = tc * 8;
        pyl = pix_y(r0);      pyh = pix_y(r0 + 31);
        pxh = pix_x(c0);      pxl = pix_x(c0 + 7);
    } else {                         // 7 rows (k) x 30 cols (lane)
        r0 = 128;  c0 = (b - 120) * 30;
        pyl = pix_y(128);     pyh = pix_y(134);
        pxh = pix_x(c0);      pxl = pix_x(c0 + 29);
    }

    // ---- phase 2: cull (warp w owns faces [w*flen, w*flen+n)) ----
    int fbeg = w * flen;
    int n = F - fbeg;
    if (n > flen) n = flen;
    if (n < 0) n = 0;

    int* slw = sl + w * 128;
    int nlist = 0;
    for (int g = 0; g < n; g += 32) {
        int f = g + lane;
        bool pass = false;
        if (f < n) {
            float4 bb = sbb[fbeg + f];
            pass = (bb.y >= pxl) & (bb.x <= pxh) & (bb.w >= pyl) & (bb.z <= pyh);
        }
        unsigned m = __ballot_sync(0xffffffffu, pass);
        if (pass) slw[nlist + __popc(m & ((1u << lane) - 1u))] = f;
        nlist += __popc(m);
    }
    __syncthreads();   // sbb dead from here; zf may be written

    // ---- phase 3: raster this warp's face slice over the tile ----
    float zr[8];
    int   fr[8];
    #pragma unroll
    for (int k = 0; k < 8; k++) { zr[k] = CUDART_INF_F; fr[k] = -1; }

    if (cfgA) {
        float py = pix_y(r0 + lane);
        float px[8];
        #pragma unroll
        for (int k = 0; k < 8; k++) px[k] = pix_x(c0 + k);

        for (int j = 0; j < nlist; j++) {
            int f = fbeg + slw[j];
            float4 A = sc[f * 3 + 0];
            float4 B = sc[f * 3 + 1];
            float4 C = sc[f * 3 + 2];

            float t0 = fmaf(A.y, py, A.z);   // gy0*py + k0
            float t1 = fmaf(B.x, py, B.y);   // gy1*py + k1
            float t2 = fmaf(B.w, py, C.x);   // gy2*py + k2
            float tz = fmaf(C.z, py, C.w);   // zy*py + zk

            #pragma unroll
            for (int k = 0; k < 8; k++) {
                float b0 = fmaf(A.x, px[k], t0);
                float b1 = fmaf(A.w, px[k], t1);
                float b2 = fmaf(B.z, px[k], t2);
                float zp = fmaf(C.y, px[k], tz);
                float mm = fminf(fminf(b0, b1), b2);
                float zc = (mm >= 0.0f) ? zp : CUDART_INF_F;
                if (zc < zr[k]) { zr[k] = zc; fr[k] = f; }
            }
        }
    } else {
        int cl = (lane < 30) ? lane : 29;    // lanes 30,31 compute garbage, never stored
        float px = pix_x(c0 + cl);
        float py[7];
        #pragma unroll
        for (int k = 0; k < 7; k++) py[k] = pix_y(128 + k);

        for (int j = 0; j < nlist; j++) {
            int f = fbeg + slw[j];
            float4 A = sc[f * 3 + 0];
            float4 B = sc[f * 3 + 1];
            float4 C = sc[f * 3 + 2];

            float u0 = fmaf(A.x, px, A.z);   // gx0*px + k0
            float u1 = fmaf(A.w, px, B.y);   // gx1*px + k1
            float u2 = fmaf(B.z, px, C.x);   // gx2*px + k2
            float uz = fmaf(C.y, px, C.w);   // zx*px + zk

            #pragma unroll
            for (int k = 0; k < 7; k++) {
                float b0 = fmaf(A.y, py[k], u0);
                float b1 = fmaf(B.x, py[k], u1);
                float b2 = fmaf(B.w, py[k], u2);
                float zp = fmaf(C.z, py[k], uz);
                float mm = fminf(fminf(b0, b1), b2);
                float zc = (mm >= 0.0f) ? zp : CUDART_INF_F;
                if (zc < zr[k]) { zr[k] = zc; fr[k] = f; }
            }
        }
    }

    // publish candidates: zf[k][w][lane] (lane-contiguous -> conflict-free)
    #pragma unroll
    for (int k = 0; k < 8; k++)
        zf[(k * NW + w) * 32 + lane] = make_float2(zr[k], __int_as_float(fr[k]));
    __syncthreads();

    // ---- phase 4: per-pixel reduction over the 16 splits + output ----
    int t = threadIdx.x;
    if (t < 256) {
        int lane_ = t & 31;
        int k_    = t >> 5;
        bool valid;
        int row, col;
        if (cfgA) { valid = true;                          row = r0 + lane_; col = c0 + k_; }
        else      { valid = (k_ < 7) && (lane_ < 30);      row = 128 + k_;   col = c0 + lane_; }

        if (valid) {
            float zb = CUDART_INF_F;
            int   fv = -1;
            // ascending split order + strict '<'  ==  lowest-index tie-break
            #pragma unroll
            for (int ww = 0; ww < NW; ww++) {
                float2 v = zf[(k_ * NW + ww) * 32 + lane_];
                if (v.x < zb) { zb = v.x; fv = __float_as_int(v.y); }
            }

            float bb0 = -1.0f, bb1 = -1.0f, bb2 = -1.0f;
            if (fv >= 0) {
                float4 A = sc[fv * 3 + 0];
                float4 B = sc[fv * 3 + 1];
                float k2 = sc[fv * 3 + 2].x;
                float px_ = pix_x(col);
                float py_ = pix_y(row);
                if (cfgA) {   // identical op order to cfgA raster loop
                    bb0 = fmaf(A.x, px_, fmaf(A.y, py_, A.z));
                    bb1 = fmaf(A.w, px_, fmaf(B.x, py_, B.y));
                    bb2 = fmaf(B.z, px_, fmaf(B.w, py_, k2));
                } else {      // identical op order to cfgB raster loop
                    bb0 = fmaf(A.y, py_, fmaf(A.x, px_, A.z));
                    bb1 = fmaf(B.x, py_, fmaf(A.w, px_, B.y));
                    bb2 = fmaf(B.w, py_, fmaf(B.z, px_, k2));
                }
            }

            int p = row * W_OUT + col;
            out[p] = (float)fv;
            float* bary = out + NPIX + 3 * p;
            bary[0] = bb0;
            bary[1] = bb1;
            bary[2] = bb2;
        }
    }
}

extern "C" void kernel_launch(void* const* d_in, const int* in_sizes, int n_in,
                              void* d_out, int out_size) {
    const float* verts = (const float*)d_in[0];
    const int*   faces = (const int*)d_in[1];
    int F = in_sizes[1] / 3;
    if (F > MAXF) F = MAXF;
    int flen = (F + NW - 1) / NW;
    if (flen < 1) flen = 1;
    if (flen > 128) flen = 128;

    cudaFuncSetAttribute(raster_one_kernel,
                         cudaFuncAttributeMaxDynamicSharedMemorySize, SMEM_TOTAL);
    raster_one_kernel<<<NBLK, BLOCKT, SMEM_TOTAL>>>(
        verts, faces, (float*)d_out, F, flen);
}